// round 16
// baseline (speedup 1.0000x reference)
#include <cuda_runtime.h>
#include <cuda_fp16.h>
#include <math.h>

#define NA   4096
#define FDIM 128
#define NH   4
#define DH   32
#define KNN  15
#define NKR  50
#define NL   6
#define NEDGE (NA*KNN)
#define WT   16
#define TROWS 4096
#define TG_ROWS 64
#define ECOL  256          // table cols, interleaved: [ (ek_c, ev_c) x 128 ]

// ---------------- scratch (static device globals; no runtime alloc) --------
// Dead code eliminated: reference's vector channel v never reaches the output.
// Edge filter tabulated over scalar d (4096 rows/layer, lerp), (ek,ev) interleaved.
// QKV via m16n8k16 HMMA; KNN via histogram radix-select with parallel rank.
__device__ float  d_s[NA*FDIM];
__device__ __half d_sh[NA*FDIM];           // fp16 shadow of s (HMMA A operand)
__device__ float  d_o[NA*FDIM];
__device__ float  d_q[NA*FDIM];
__device__ __half d_kvh[NA*256];           // fp16 interleaved (k_f, val_f) pairs
__device__ __half d_tab[NL*TROWS*ECOL];    // fp16 interleaved (ek_f, ev_f) pairs
__device__ uint2  d_w16[NL*48*8*32];       // B-fragments: [l][nblk8][kblk16][lane]
__device__ float  d_cut[NEDGE];
__device__ float  d_dist[NEDGE];
__device__ int    d_idx[NEDGE];
__device__ float  d_h[NA];

// ---------------- init ------------------------------------------------------
__global__ void init_kernel(const int* __restrict__ Z, const float* __restrict__ emb) {
    int t = blockIdx.x * blockDim.x + threadIdx.x;
    if (t < NA*FDIM) {
        int i = t / FDIM, f = t % FDIM;
        float v = emb[Z[i]*FDIM + f];
        d_s[t]  = v;
        d_sh[t] = __float2half(v);
        d_o[t]  = 0.f;
    }
}

// ---------------- weight converter: fp32 -> fp16 B-fragment layout ----------
__global__ void wcvt_kernel(const float* __restrict__ Wq, const float* __restrict__ Wk,
                            const float* __restrict__ Wv) {
    int t = blockIdx.x*256 + threadIdx.x;
    if (t >= NL*48*8*32) return;
    int lane = t & 31;
    int kblk = (t >> 5) & 7;
    int nblk = (t >> 8) % 48;
    int l    = t / (48*8*32);
    int n  = nblk*8 + (lane >> 2);
    int k0 = kblk*16 + (lane & 3)*2;

    float w[4];
    #pragma unroll
    for (int j = 0; j < 4; j++) {
        int k = k0 + (j >> 1)*8 + (j & 1);
        float v;
        if (n < 128)      v = Wq[l*FDIM*FDIM + k*FDIM + n];
        else if (n < 256) v = Wk[l*FDIM*FDIM + k*FDIM + (n - 128)];
        else              v = Wv[l*FDIM*384  + k*384  + (n - 256)];
        w[j] = v;
    }
    __half2 h0 = __floats2half2_rn(w[0], w[1]);
    __half2 h1 = __floats2half2_rn(w[2], w[3]);
    uint2 out;
    out.x = *(unsigned*)&h0;
    out.y = *(unsigned*)&h1;
    d_w16[t] = out;
}

// ---------------- edge-filter table builder (interleaved output) ------------
#define TG_SMEM ((50*ECOL + ECOL + TG_ROWS*16 + TG_ROWS) * 4)

__global__ __launch_bounds__(256) void tablegen_kernel(const float* __restrict__ Wek,
                                                       const float* __restrict__ bek,
                                                       const float* __restrict__ Wev,
                                                       const float* __restrict__ bev) {
    extern __shared__ float sm[];
    float* Ws    = sm;
    float* biasS = sm + 50*ECOL;
    float* taps  = biasS + ECOL;
    int*   kbS   = (int*)(taps + TG_ROWS*16);

    int l = blockIdx.y, rb = blockIdx.x;
    int tid = threadIdx.x;

    {
        float4* Ws4 = (float4*)Ws;
        const float4* Wek4 = (const float4*)(Wek + l*50*FDIM);
        const float4* Wev4 = (const float4*)(Wev + l*50*384);
        for (int q = tid; q < 50*64; q += 256) {
            int row = q >> 6, c4 = q & 63;
            Ws4[q] = (c4 < 32) ? Wek4[row*32 + c4] : Wev4[row*96 + (c4 - 32)];
        }
        if (tid < 64) {
            float4 b = (tid < 32) ? ((const float4*)(bek + l*FDIM))[tid]
                                  : ((const float4*)(bev + l*384))[tid - 32];
            ((float4*)biasS)[tid] = b;
        }
    }
    for (int u = tid; u < TG_ROWS*16; u += 256) {
        int r = u >> 4, t = u & 15;
        float d  = (float)(rb*TG_ROWS + r) * (5.0f/4095.0f);
        float fi = d * (49.0f/5.0f);
        int kb = (int)floorf(fi + 0.5f) - 7;
        kb = max(0, min(50 - WT, kb));
        if (t == 0) kbS[r] = kb;
        float mu  = (float)(kb + t) * (5.0f/49.0f);
        float df  = d - mu;
        float cut = 0.5f*(cosf(0.62831853071795864769f*d) + 1.0f);
        taps[u] = expf(-df*df*50.0f) * cut;
    }
    __syncthreads();

    int c = tid;
    float bias = biasS[c];
    int dst = (c < 128) ? (2*c) : (2*(c - 128) + 1);
    for (int r = 0; r < TG_ROWS; r++) {
        int kb = kbS[r];
        const float* tp = taps + r*16;
        const float* wp = Ws + kb*ECOL + c;
        float acc = 0.f;
        #pragma unroll
        for (int t = 0; t < 16; t++)
            acc = fmaf(tp[t], wp[t*ECOL], acc);
        float x = acc + bias;
        float y = x / (1.f + __expf(-x));
        d_tab[((size_t)l*TROWS + rb*TG_ROWS + r)*ECOL + dst] = __float2half(y);
    }
}

// ---------------- KNN via histogram radix-select (parallel rank) ------------
#define KNN_CAP 128

__global__ __launch_bounds__(256) void knn_kernel(const float* __restrict__ R) {
    __shared__ int   hist[256];
    __shared__ int   warpsum[8];
    __shared__ int   s_cutbin;
    __shared__ int   s_cnt;
    __shared__ float cv[KNN_CAP];
    __shared__ int   cjj[KNN_CAP];
    __shared__ int   sidx[KNN];

    int i = blockIdx.x, t = threadIdx.x;
    int lane = t & 31, wrp = t >> 5;
    float rx = R[i*3], ry = R[i*3+1], rz = R[i*3+2];

    float dr[16];
    int   bn[16];
    hist[t] = 0;
    if (t == 0) s_cnt = 0;
    __syncthreads();

    #pragma unroll
    for (int u = 0; u < 16; u++) {
        int j = t + u*256;
        float x = R[j*3]   - rx;
        float y = R[j*3+1] - ry;
        float z = R[j*3+2] - rz;
        float d2 = x*x + y*y + z*z;
        if (j == i) d2 = 1e9f;
        dr[u] = d2;
        int b = (int)fminf(d2 * 0.25f, 255.0f);
        bn[u] = b;
        atomicAdd(&hist[b], 1);
    }
    __syncthreads();

    {
        int h = hist[t];
        int sc = h;
        #pragma unroll
        for (int off = 1; off < 32; off <<= 1) {
            int o = __shfl_up_sync(0xffffffffu, sc, off);
            if (lane >= off) sc += o;
        }
        if (lane == 31) warpsum[wrp] = sc;
        __syncthreads();
        int wpre = 0;
        #pragma unroll
        for (int w2 = 0; w2 < 8; w2++)
            wpre += (w2 < wrp) ? warpsum[w2] : 0;
        int gcum = wpre + sc;
        if (gcum >= KNN && gcum - h < KNN) s_cutbin = t;
    }
    __syncthreads();

    int cutbin = s_cutbin;
    #pragma unroll
    for (int u = 0; u < 16; u++) {
        if (bn[u] <= cutbin) {
            int p = atomicAdd(&s_cnt, 1);
            if (p < KNN_CAP) { cv[p] = dr[u]; cjj[p] = t + u*256; }
        }
    }
    __syncthreads();
    int cnt = min(s_cnt, KNN_CAP);

    for (int p = t; p < cnt; p += 256) {
        float v = cv[p]; int j = cjj[p];
        int rank = 0;
        for (int qq = 0; qq < cnt; qq++) {
            float vq = cv[qq]; int jq = cjj[qq];
            rank += (vq < v || (vq == v && jq < j)) ? 1 : 0;
        }
        if (rank < KNN) sidx[rank] = j;
    }
    __syncthreads();

    if (t < KNN) {
        int j = sidx[t];
        float vx = R[j*3]   - rx;
        float vy = R[j*3+1] - ry;
        float vz = R[j*3+2] - rz;
        float dd = sqrtf(vx*vx + vy*vy + vz*vz + 1e-12f);
        int e = i*KNN + t;
        d_idx[e] = j;
        float c = (dd <= 5.f) ? 0.5f*(cosf(0.62831853071795864769f*dd) + 1.f) : 0.f;
        d_cut[e]  = c;
        d_dist[e] = dd;
    }
}

// ---------------- QKV via m16n8k16 HMMA: 32x32 block tiles ------------------
// grid (NA/32, 12), 128 thr. Warp w: rows (w&1)*16, cols (w>>1)*16 (2 n-blocks).
__global__ __launch_bounds__(128) void qkv_mma(int l) {
    int bm = blockIdx.x, bn = blockIdx.y;
    int w  = threadIdx.x >> 5, lane = threadIdx.x & 31;
    int r0 = bm*32 + (w & 1)*16 + (lane >> 2);
    int c0 = (lane & 3)*2;
    int nbase = bn*32 + (w >> 1)*16;      // global col base for this warp

    unsigned A[8][4];
    #pragma unroll
    for (int kb = 0; kb < 8; kb++) {
        const __half* p0 = d_sh + r0*FDIM + kb*16 + c0;
        const __half* p1 = d_sh + (r0+8)*FDIM + kb*16 + c0;
        A[kb][0] = *(const unsigned*)p0;
        A[kb][1] = *(const unsigned*)p1;
        A[kb][2] = *(const unsigned*)(p0 + 8);
        A[kb][3] = *(const unsigned*)(p1 + 8);
    }

    const uint2* Wp = d_w16 + ((size_t)(l*48 + (nbase >> 3)) * 8) * 32;

    #pragma unroll
    for (int nb = 0; nb < 2; nb++) {
        float f0 = 0.f, f1 = 0.f, f2 = 0.f, f3 = 0.f;
        #pragma unroll
        for (int kb = 0; kb < 8; kb++) {
            uint2 bv = Wp[(nb*8 + kb)*32 + lane];
            asm volatile(
                "mma.sync.aligned.m16n8k16.row.col.f32.f16.f16.f32 "
                "{%0,%1,%2,%3}, {%4,%5,%6,%7}, {%8,%9}, {%0,%1,%2,%3};"
                : "+f"(f0), "+f"(f1), "+f"(f2), "+f"(f3)
                : "r"(A[kb][0]), "r"(A[kb][1]), "r"(A[kb][2]), "r"(A[kb][3]),
                  "r"(bv.x), "r"(bv.y));
        }
        int ngl = nbase + nb*8 + c0;
        if (ngl < 128) {
            *(float2*)&d_q[r0*FDIM + ngl]     = make_float2(f0, f1);
            *(float2*)&d_q[(r0+8)*FDIM + ngl] = make_float2(f2, f3);
        } else if (ngl < 256) {
            int c = ngl - 128;
            d_kvh[(size_t)r0*256 + 2*c]         = __float2half(f0);
            d_kvh[(size_t)r0*256 + 2*c + 2]     = __float2half(f1);
            d_kvh[(size_t)(r0+8)*256 + 2*c]     = __float2half(f2);
            d_kvh[(size_t)(r0+8)*256 + 2*c + 2] = __float2half(f3);
        } else {
            int c = ngl - 256;
            d_kvh[(size_t)r0*256 + 2*c + 1]     = __float2half(f0);
            d_kvh[(size_t)r0*256 + 2*c + 3]     = __float2half(f1);
            d_kvh[(size_t)(r0+8)*256 + 2*c + 1] = __float2half(f2);
            d_kvh[(size_t)(r0+8)*256 + 2*c + 3] = __float2half(f3);
        }
    }
}

// ---------------- fused attention message (reg softmax, paired gathers) -----
__global__ __launch_bounds__(512) void message_kernel(const __half* __restrict__ tabL) {
    __shared__ float scut[4][KNN];
    __shared__ int   si0[4][KNN];
    __shared__ float sfr[4][KNN];
    __shared__ int   sj[4][KNN];

    int sub = threadIdx.x >> 7;
    int f   = threadIdx.x & 127;
    int i   = blockIdx.x*4 + sub;

    if (f < KNN) {
        int e = i*KNN + f;
        sj[sub][f]   = d_idx[e];
        scut[sub][f] = d_cut[e];
        float fi = fminf(d_dist[e] * (4095.0f/5.0f), 4095.0f);
        int i0 = min((int)fi, 4094);
        si0[sub][f] = i0;
        sfr[sub][f] = fi - (float)i0;
    }
    __syncthreads();

    float q = d_q[i*FDIM + f];
    float prod[KNN], logit[KNN];

    #pragma unroll
    for (int k = 0; k < KNN; k++) {
        int j = sj[sub][k];
        int i0 = si0[sub][k];
        float fr = sfr[sub][k];
        __half2 kv = *(const __half2*)(d_kvh + (size_t)j*256 + 2*f);
        __half2 t0 = *(const __half2*)(tabL + (size_t)i0*ECOL + 2*f);
        __half2 t1 = *(const __half2*)(tabL + (size_t)(i0+1)*ECOL + 2*f);
        float kf = __half2float(__low2half(kv));
        float va = __half2float(__high2half(kv));
        float ek0 = __half2float(__low2half(t0)),  ev0 = __half2float(__high2half(t0));
        float ek1 = __half2float(__low2half(t1)),  ev1 = __half2float(__high2half(t1));
        float ek = fmaf(fr, ek1 - ek0, ek0);
        float ev = fmaf(fr, ev1 - ev0, ev0);
        prod[k] = va * ev;
        float p = q * kf * ek;
        #pragma unroll
        for (int off = 16; off; off >>= 1) p += __shfl_xor_sync(0xffffffffu, p, off);
        logit[k] = p * 0.125f;
    }

    float mx = logit[0];
    #pragma unroll
    for (int k = 1; k < KNN; k++) mx = fmaxf(mx, logit[k]);
    float sum = 0.f;
    #pragma unroll
    for (int k = 0; k < KNN; k++) { logit[k] = expf(logit[k] - mx); sum += logit[k]; }
    float inv = 1.f / sum;

    float ds = 0.f;
    #pragma unroll
    for (int k = 0; k < KNN; k++)
        ds = fmaf(logit[k] * inv * scut[sub][k], prod[k], ds);

    float sn = d_s[i*FDIM + f] + ds;
    d_s[i*FDIM + f]  = sn;
    d_sh[i*FDIM + f] = __float2half(sn);
    d_o[i*FDIM + f] += ds;
}

// ---------------- layernorm + readout ---------------------------------------
__global__ void readout_kernel(const float* __restrict__ ln_g, const float* __restrict__ ln_b,
                               const float* __restrict__ Wo1,  const float* __restrict__ Wo2) {
    __shared__ float red[128];
    __shared__ float son[128];
    int i = blockIdx.x, f = threadIdx.x;
    float x = d_o[i*FDIM + f];

    red[f] = x; __syncthreads();
    for (int s = 64; s > 0; s >>= 1) { if (f < s) red[f] += red[f+s]; __syncthreads(); }
    float mean = red[0] * (1.f/128.f);
    __syncthreads();

    float dx = x - mean;
    red[f] = dx*dx; __syncthreads();
    for (int s = 64; s > 0; s >>= 1) { if (f < s) red[f] += red[f+s]; __syncthreads(); }
    float var = red[0] * (1.f/128.f);
    __syncthreads();

    float on = dx * (1.f / sqrtf(var + 1e-5f)) * ln_g[f] + ln_b[f];
    son[f] = on; __syncthreads();

    float acc = 0.f;
    #pragma unroll 8
    for (int g = 0; g < 128; g++) acc = fmaf(son[g], Wo1[g*FDIM + f], acc);
    float tb = acc / (1.f + expf(-acc));
    red[f] = tb * Wo2[f];
    __syncthreads();
    for (int s = 64; s > 0; s >>= 1) { if (f < s) red[f] += red[f+s]; __syncthreads(); }
    if (f == 0) d_h[i] = red[0];
}

__global__ void sum_kernel(float* __restrict__ out) {
    __shared__ double rd[256];
    int t = threadIdx.x;
    double a = 0.0;
    for (int i = t; i < NA; i += 256) a += (double)d_h[i];
    rd[t] = a; __syncthreads();
    for (int s = 128; s > 0; s >>= 1) { if (t < s) rd[t] += rd[t+s]; __syncthreads(); }
    if (t == 0) out[0] = (float)rd[0];
}

// ---------------- launch ------------------------------------------------------
extern "C" void kernel_launch(void* const* d_in, const int* in_sizes, int n_in,
                              void* d_out, int out_size) {
    const int*   Z    = (const int*)  d_in[0];
    const float* R    = (const float*)d_in[1];
    const float* emb  = (const float*)d_in[3];
    const float* Wq   = (const float*)d_in[4];
    const float* Wk   = (const float*)d_in[5];
    const float* Wv   = (const float*)d_in[6];
    const float* We_k = (const float*)d_in[7];
    const float* be_k = (const float*)d_in[8];
    const float* We_v = (const float*)d_in[9];
    const float* be_v = (const float*)d_in[10];
    const float* ln_g = (const float*)d_in[11];
    const float* ln_b = (const float*)d_in[12];
    const float* Wo1  = (const float*)d_in[13];
    const float* Wo2  = (const float*)d_in[14];
    float* out = (float*)d_out;

    static __half* tabp = nullptr;
    static cudaStream_t s1 = nullptr;
    static cudaEvent_t evF = nullptr, evI = nullptr, evT = nullptr;
    if (!tabp) {
        cudaGetSymbolAddress((void**)&tabp, d_tab);
        cudaFuncSetAttribute(tablegen_kernel, cudaFuncAttributeMaxDynamicSharedMemorySize, TG_SMEM);
        cudaStreamCreateWithFlags(&s1, cudaStreamNonBlocking);
        cudaEventCreateWithFlags(&evF, cudaEventDisableTiming);
        cudaEventCreateWithFlags(&evI, cudaEventDisableTiming);
        cudaEventCreateWithFlags(&evT, cudaEventDisableTiming);
    }

    // fork s1 (capture-safe): tablegen + wcvt + qkv(0) hidden under knn
    cudaEventRecord(evF, 0);
    cudaStreamWaitEvent(s1, evF, 0);
    tablegen_kernel<<<dim3(TROWS/TG_ROWS, NL), 256, TG_SMEM, s1>>>(We_k, be_k, We_v, be_v);
    wcvt_kernel<<<(NL*48*8*32 + 255)/256, 256, 0, s1>>>(Wq, Wk, Wv);

    init_kernel<<<(NA*FDIM + 255)/256, 256>>>(Z, emb);
    cudaEventRecord(evI, 0);
    cudaStreamWaitEvent(s1, evI, 0);
    qkv_mma<<<dim3(NA/32, 12), 128, 0, s1>>>(0);
    cudaEventRecord(evT, s1);

    knn_kernel<<<NA, 256>>>(R);
    cudaStreamWaitEvent(0, evT, 0);

    for (int l = 0; l < NL; l++) {
        if (l > 0) qkv_mma<<<dim3(NA/32, 12), 128>>>(l);
        message_kernel<<<NA/4, 512>>>(tabp + (size_t)l*TROWS*ECOL);
    }

    readout_kernel<<<NA, 128>>>(ln_g, ln_b, Wo1, Wo2);
    sum_kernel<<<1, 256>>>(out);
}